// round 16
// baseline (speedup 1.0000x reference)
#include <cuda_runtime.h>
#include <cuda_bf16.h>
#include <math.h>
#include <stdint.h>

#define NROWS 8192
#define FIN   128
#define FOUT  64
#define BI    32
#define TILES 64
#define L2E 1.4426950408889634f
#define PB   272                 // WhT smem row pitch in bytes (136 bf16)

// attn smem map (bytes): Wh 2 bufs x (2 planes x 17408) = 69632, lred 512
#define SM_WH   0
#define SM_LR   69632
#define SM_TOTB 70144

typedef unsigned long long ull;

__device__ float g_Wh1[NROWS];          // prescaled by L2E
__device__ float g_Wh2[NROWS];          // prescaled by L2E
__device__ __nv_bfloat16 g_WhT_hi[FOUT * NROWS];
__device__ __nv_bfloat16 g_WhT_lo[FOUT * NROWS];

// ---- helpers ----------------------------------------------------------------
__device__ __forceinline__ uint32_t s2u(const void* p) {
    uint32_t a;
    asm("{.reg .u64 t; cvta.to.shared.u64 t,%1; cvt.u32.u64 %0,t;}" : "=r"(a) : "l"(p));
    return a;
}
__device__ __forceinline__ float ex2f(float x) {
    float y; asm("ex2.approx.ftz.f32 %0,%1;" : "=f"(y) : "f"(x)); return y;
}
__device__ __forceinline__ uint32_t bf2(float a, float b) {   // lo=a, hi=b
    uint32_t r; asm("cvt.rn.bf16x2.f32 %0,%2,%1;" : "=r"(r) : "f"(a), "f"(b)); return r;
}
__device__ __forceinline__ void cpasync16(uint32_t d, const void* s) {
    asm volatile("cp.async.cg.shared.global [%0],[%1],16;" :: "r"(d), "l"(s));
}
__device__ __forceinline__ void ldsm4(uint32_t* r, uint32_t a) {
    asm volatile("ldmatrix.sync.aligned.m8n8.x4.shared.b16 {%0,%1,%2,%3},[%4];"
                 : "=r"(r[0]), "=r"(r[1]), "=r"(r[2]), "=r"(r[3]) : "r"(a));
}
__device__ __forceinline__ void mmabf(float* d, const uint32_t* a, const uint32_t* b) {
    asm volatile("mma.sync.aligned.m16n8k16.row.col.f32.bf16.bf16.f32 "
                 "{%0,%1,%2,%3},{%4,%5,%6,%7},{%8,%9},{%0,%1,%2,%3};"
                 : "+f"(d[0]), "+f"(d[1]), "+f"(d[2]), "+f"(d[3])
                 : "r"(a[0]), "r"(a[1]), "r"(a[2]), "r"(a[3]), "r"(b[0]), "r"(b[1]));
}
__device__ __forceinline__ ull packf2(float a, float b) {
    ull r;
    asm("mov.b64 %0,{%1,%2};" : "=l"(r) : "r"(__float_as_uint(a)), "r"(__float_as_uint(b)));
    return r;
}
__device__ __forceinline__ void fmaf2(ull& acc, ull a, ull b) {
    asm("fma.rn.f32x2 %0,%1,%2,%0;" : "+l"(acc) : "l"(a), "l"(b));
}
__device__ __forceinline__ void unpackf2(ull v, float& lo, float& hi) {
    uint32_t l, h;
    asm("mov.b64 {%0,%1},%2;" : "=r"(l), "=r"(h) : "l"(v));
    lo = __uint_as_float(l); hi = __uint_as_float(h);
}

// masked exp (wh1/wh2 pre-scaled by L2E): p = adj ? 2^(max(z, 0.2z)) : 0
__device__ __forceinline__ float mexp(float wh1, float wh2, int a) {
    float z = wh1 + wh2;
    float t = fmaxf(z, 0.2f * z);
    if (a == 0) t = __int_as_float(0xff800000);
    return ex2f(t);
}

// ---------------------------------------------------------------------------
// Fused prep (32 rows/block, grid 256): Wh = x@W -> WhT hi/lo, Wh1*L2E, Wh2*L2E
// ---------------------------------------------------------------------------
__global__ __launch_bounds__(256) void wh_fused(const float* __restrict__ x,
                                                const float* __restrict__ W,
                                                const float* __restrict__ a) {
    extern __shared__ float shm[];
    float* xs = shm;                  // 32 x 132 = 4224
    float* Ws = shm + 4224;           // 128 x 64 = 8192
    float* av = shm + 4224 + 8192;    // 128
    int tid = threadIdx.x;
    int row0 = blockIdx.x * 32;

    for (int u = tid; u < 1024; u += 256) {
        int rr = u >> 5, cc = u & 31;
        float4 v = ((const float4*)(x + (size_t)(row0 + rr) * FIN))[cc];
        *(float4*)(xs + rr * 132 + cc * 4) = v;
    }
    for (int u = tid; u < 2048; u += 256)
        ((float4*)Ws)[u] = ((const float4*)W)[u];
    if (tid < 128) av[tid] = a[tid];
    __syncthreads();

    int tr = tid >> 4, tc = tid & 15;       // tr 0..15 -> rows tr*2+i
    ull acc[2][2] = {{0ull, 0ull}, {0ull, 0ull}};
    const ulonglong2* W2 = (const ulonglong2*)Ws;
#pragma unroll 4
    for (int k = 0; k < FIN; k++) {
        ulonglong2 wv = W2[k * 16 + tc];
#pragma unroll
        for (int i = 0; i < 2; i++) {
            float xv = xs[(tr * 2 + i) * 132 + k];
            ull xp = packf2(xv, xv);
            fmaf2(acc[i][0], xp, wv.x);
            fmaf2(acc[i][1], xp, wv.y);
        }
    }
    float o[2][4];
#pragma unroll
    for (int i = 0; i < 2; i++) {
        unpackf2(acc[i][0], o[i][0], o[i][1]);
        unpackf2(acc[i][1], o[i][2], o[i][3]);
    }
    __syncthreads();
    float* s2 = xs;                  // reuse: [64 f][pitch 33], 2112 floats
#pragma unroll
    for (int i = 0; i < 2; i++)
#pragma unroll
        for (int j = 0; j < 4; j++)
            s2[(tc * 4 + j) * 33 + tr * 2 + i] = o[i][j];
    __syncthreads();

    {
        int f = tid >> 2, seg = tid & 3;     // f 0..63, seg -> cols seg*8..+7
        const float* src = s2 + f * 33 + seg * 8;
        uint32_t hi[4], lo[4];
#pragma unroll
        for (int j = 0; j < 4; j++) {
            float v0 = src[2 * j], v1 = src[2 * j + 1];
            uint32_t hh = bf2(v0, v1);
            float r0 = v0 - __uint_as_float(hh << 16);
            float r1 = v1 - __uint_as_float(hh & 0xffff0000u);
            hi[j] = hh; lo[j] = bf2(r0, r1);
        }
        size_t o0 = ((size_t)f * NROWS + row0 + seg * 8) * 2;
        *(uint4*)((char*)g_WhT_hi + o0) = make_uint4(hi[0], hi[1], hi[2], hi[3]);
        *(uint4*)((char*)g_WhT_lo + o0) = make_uint4(lo[0], lo[1], lo[2], lo[3]);
    }
    {
        int row = tid >> 3, sub = tid & 7;   // row 0..31, 8 lanes per row
        float s1 = 0.f, sB = 0.f;
#pragma unroll
        for (int k = 0; k < 8; k++) {
            int f = sub * 8 + k;
            float v = s2[f * 33 + row];
            s1 += v * av[f];
            sB += v * av[64 + f];
        }
        s1 += __shfl_xor_sync(0xffffffffu, s1, 1);
        s1 += __shfl_xor_sync(0xffffffffu, s1, 2);
        s1 += __shfl_xor_sync(0xffffffffu, s1, 4);
        sB += __shfl_xor_sync(0xffffffffu, sB, 1);
        sB += __shfl_xor_sync(0xffffffffu, sB, 2);
        sB += __shfl_xor_sync(0xffffffffu, sB, 4);
        if (sub == 0) {
            g_Wh1[row0 + row] = s1 * L2E;    // prescaled
            g_Wh2[row0 + row] = sB * L2E;    // prescaled
        }
    }
}

// ---------------------------------------------------------------------------
// attn: EXACT R15 kernel (128.99us best). BI=32, grid 256, 2 blocks/SM.
// 8 warps = 2m x 4k; n=64 unsplit. Phase-1 in A-fragment registers.
// ---------------------------------------------------------------------------
__global__ __launch_bounds__(256, 2) void attn_kernel(const int* __restrict__ adj,
                                                      float* __restrict__ out) {
    extern __shared__ char smc[];
    uint32_t smb = s2u(smc);
    float* lred = (float*)(smc + SM_LR);      // [4 kk][32 rows]

    int tid = threadIdx.x;
    int warp = tid >> 5, lane = tid & 31;
    int g = lane >> 2, tg = lane & 3;
    int mi = warp & 1, kk = warp >> 1;        // 2 m-strips x 4 k-chunks
    int i0 = blockIdx.x * BI;
    int row0 = i0 + mi * 16 + g;              // thread's two rows: row0, row0+8

    float wh1a = g_Wh1[row0];
    float wh1b = g_Wh1[row0 + 8];

    const int* ar0 = adj + (size_t)row0 * NROWS;
    const int* ar1 = ar0 + (size_t)8 * NROWS;

    // B ldsm addressing (proven layout)
    uint32_t boff = (uint32_t)(((lane & 7) + 8 * (lane >> 4)) * PB + ((lane >> 3) & 1) * 16);
    uint32_t bBase = smb + SM_WH + boff + (uint32_t)kk * 64;

    float acc[8][4];
#pragma unroll
    for (int i = 0; i < 8; i++)
#pragma unroll
        for (int j = 0; j < 4; j++) acc[i][j] = 0.f;

    // cp.async geometry: Wh 4 chunks/thread/plane
    uint32_t dsto[4], srco[4];
#pragma unroll
    for (int u = 0; u < 4; u++) {
        int idx = u * 256 + tid;
        int row = idx >> 4, ch = idx & 15;
        dsto[u] = (uint32_t)(row * PB + ch * 16);
        srco[u] = (uint32_t)((row * NROWS + ch * 8) * 2);
    }

    // prologue: cp.async Wh(0) -> buf0
    {
        const char* ph = (const char*)g_WhT_hi;
        const char* pl = (const char*)g_WhT_lo;
        uint32_t d0 = smb + SM_WH;
#pragma unroll
        for (int u = 0; u < 4; u++) cpasync16(d0 + dsto[u], ph + srco[u]);
#pragma unroll
        for (int u = 0; u < 4; u++) cpasync16(d0 + 17408 + dsto[u], pl + srco[u]);
        asm volatile("cp.async.commit_group;" ::: "memory");
    }

    float lsum0 = 0.f, lsum1 = 0.f;

    for (int t = 0; t < TILES; ++t) {
        // ---- phase 1: A fragments in registers (adj direct) ----
        uint32_t ah[2][4], al[2][4];
        int jb = (t << 7) + kk * 32;
#pragma unroll
        for (int s = 0; s < 4; s++) {          // s = step*2 + half
            int cj = jb + s * 8 + tg * 2;
            int2 A0 = *(const int2*)(ar0 + cj);
            int2 A1 = *(const int2*)(ar1 + cj);
            float2 w2 = *(const float2*)(g_Wh2 + cj);
            float p00 = mexp(wh1a, w2.x, A0.x);
            float p01 = mexp(wh1a, w2.y, A0.y);
            float p10 = mexp(wh1b, w2.x, A1.x);
            float p11 = mexp(wh1b, w2.y, A1.y);
            lsum0 += p00 + p01;
            lsum1 += p10 + p11;
            uint32_t h0 = bf2(p00, p01);
            uint32_t h1 = bf2(p10, p11);
            float r00 = p00 - __uint_as_float(h0 << 16);
            float r01 = p01 - __uint_as_float(h0 & 0xffff0000u);
            float r10 = p10 - __uint_as_float(h1 << 16);
            float r11 = p11 - __uint_as_float(h1 & 0xffff0000u);
            int st = s >> 1, hf = s & 1;
            ah[st][hf * 2 + 0] = h0;
            ah[st][hf * 2 + 1] = h1;
            al[st][hf * 2 + 0] = bf2(r00, r01);
            al[st][hf * 2 + 1] = bf2(r10, r11);
        }

        // ---- Wh(t) ready; release buffers ----
        asm volatile("cp.async.wait_group 0;" ::: "memory");
        __syncthreads();
        if (t < 63) {
            uint32_t d0 = smb + SM_WH + (uint32_t)((t + 1) & 1) * 34816;
            const char* ph = (const char*)g_WhT_hi;
            const char* pl = (const char*)g_WhT_lo;
            uint32_t j2 = (uint32_t)(t + 1) * 256;
#pragma unroll
            for (int u = 0; u < 4; u++) cpasync16(d0 + dsto[u], ph + srco[u] + j2);
#pragma unroll
            for (int u = 0; u < 4; u++) cpasync16(d0 + 17408 + dsto[u], pl + srco[u] + j2);
            asm volatile("cp.async.commit_group;" ::: "memory");
        }

        // ---- MMA(t): A regs x Wh[t&1] ----
        uint32_t wB = bBase + (uint32_t)(t & 1) * 34816;
#pragma unroll
        for (int st = 0; st < 2; st++) {
            uint32_t ko = (uint32_t)st * 32;
#pragma unroll
            for (int ng = 0; ng < 4; ng++) {
                uint32_t bh[4], bl[4];
                uint32_t ba = wB + (uint32_t)ng * (16 * PB) + ko;
                ldsm4(bh, ba);
                ldsm4(bl, ba + 17408);
                mmabf(acc[2 * ng + 0], ah[st], bh + 0);
                mmabf(acc[2 * ng + 1], ah[st], bh + 2);
                mmabf(acc[2 * ng + 0], ah[st], bl + 0);
                mmabf(acc[2 * ng + 1], ah[st], bl + 2);
                mmabf(acc[2 * ng + 0], al[st], bh + 0);
                mmabf(acc[2 * ng + 1], al[st], bh + 2);
            }
        }
    }

    // ---- epilogue ----
    lsum0 += __shfl_xor_sync(0xffffffffu, lsum0, 1);
    lsum0 += __shfl_xor_sync(0xffffffffu, lsum0, 2);
    lsum1 += __shfl_xor_sync(0xffffffffu, lsum1, 1);
    lsum1 += __shfl_xor_sync(0xffffffffu, lsum1, 2);
    int rl = mi * 16 + g;
    if (tg == 0) {
        lred[kk * 32 + rl] = lsum0;
        lred[kk * 32 + rl + 8] = lsum1;
    }
    __syncthreads();

    float* Red = (float*)(smc + SM_WH);   // reuse: 2 arrays of 32x66 floats
    if (kk == 1 || kk == 3) {
        float* R = Red + (kk >> 1) * 2112;
#pragma unroll
        for (int nb = 0; nb < 8; nb++) {
            int cl = nb * 8 + tg * 2;
            *(float2*)(R + rl * 66 + cl) = make_float2(acc[nb][0], acc[nb][1]);
            *(float2*)(R + (rl + 8) * 66 + cl) = make_float2(acc[nb][2], acc[nb][3]);
        }
    }
    __syncthreads();
    if (kk == 0 || kk == 2) {
        float* R = Red + (kk >> 1) * 2112;
#pragma unroll
        for (int nb = 0; nb < 8; nb++) {
            int cl = nb * 8 + tg * 2;
            float2 o0 = *(float2*)(R + rl * 66 + cl);
            float2 o1 = *(float2*)(R + (rl + 8) * 66 + cl);
            acc[nb][0] += o0.x; acc[nb][1] += o0.y;
            acc[nb][2] += o1.x; acc[nb][3] += o1.y;
        }
    }
    __syncthreads();
    if (kk == 2) {
        float* R = Red + 2112;
#pragma unroll
        for (int nb = 0; nb < 8; nb++) {
            int cl = nb * 8 + tg * 2;
            *(float2*)(R + rl * 66 + cl) = make_float2(acc[nb][0], acc[nb][1]);
            *(float2*)(R + (rl + 8) * 66 + cl) = make_float2(acc[nb][2], acc[nb][3]);
        }
    }
    __syncthreads();
    if (kk == 0) {
        float la = lred[rl] + lred[32 + rl] + lred[64 + rl] + lred[96 + rl];
        float lb = lred[rl + 8] + lred[32 + rl + 8] + lred[64 + rl + 8] + lred[96 + rl + 8];
        float inv0 = 1.0f / la, inv1 = 1.0f / lb;
        float* R = Red + 2112;
#pragma unroll
        for (int nb = 0; nb < 8; nb++) {
            int cl = nb * 8 + tg * 2;
            float2 o0 = *(float2*)(R + rl * 66 + cl);
            float2 o1 = *(float2*)(R + (rl + 8) * 66 + cl);
            float v0 = (acc[nb][0] + o0.x) * inv0;
            float v1 = (acc[nb][1] + o0.y) * inv0;
            float v2 = (acc[nb][2] + o1.x) * inv1;
            float v3 = (acc[nb][3] + o1.y) * inv1;
            v0 = v0 > 0.f ? v0 : (__expf(v0) - 1.f);
            v1 = v1 > 0.f ? v1 : (__expf(v1) - 1.f);
            v2 = v2 > 0.f ? v2 : (__expf(v2) - 1.f);
            v3 = v3 > 0.f ? v3 : (__expf(v3) - 1.f);
            *(float2*)(out + (size_t)(i0 + rl) * FOUT + cl) = make_float2(v0, v1);
            *(float2*)(out + (size_t)(i0 + rl + 8) * FOUT + cl) = make_float2(v2, v3);
        }
    }
}

// ---------------------------------------------------------------------------
extern "C" void kernel_launch(void* const* d_in, const int* in_sizes, int n_in,
                              void* d_out, int out_size) {
    const float* x   = (const float*)d_in[0];
    const int*   adj = (const int*)d_in[1];
    const float* W   = (const float*)d_in[2];
    const float* a   = (const float*)d_in[3];
    float* out = (float*)d_out;

    size_t smem_wh = (size_t)(4224 + 8192 + 128) * sizeof(float);
    static int attr_set = 0;
    if (!attr_set) {
        cudaFuncSetAttribute(wh_fused, cudaFuncAttributeMaxDynamicSharedMemorySize,
                             (int)smem_wh);
        cudaFuncSetAttribute(attn_kernel, cudaFuncAttributeMaxDynamicSharedMemorySize,
                             SM_TOTB);
        attr_set = 1;
    }

    wh_fused<<<NROWS / 32, 256, smem_wh>>>(x, W, a);
    attn_kernel<<<NROWS / BI, 256, SM_TOTB>>>(adj, out);
}

// round 17
// speedup vs baseline: 1.0328x; 1.0328x over previous
#include <cuda_runtime.h>
#include <cuda_fp16.h>
#include <math.h>
#include <stdint.h>

#define NROWS 8192
#define FIN   128
#define FOUT  64
#define BI    32
#define TILES 64
#define L2E 1.4426950408889634f
#define PB   272                 // WhT smem row pitch in bytes (136 fp16)

// attn smem map (bytes): Wh 2 bufs x (2 planes x 17408) = 69632, lred 512
#define SM_WH   0
#define SM_LR   69632
#define SM_TOTB 70144

typedef unsigned long long ull;

__device__ float g_Wh1[NROWS];          // prescaled by L2E
__device__ float g_Wh2[NROWS];          // prescaled by L2E
__device__ __half g_WhT_hi[FOUT * NROWS];
__device__ __half g_WhT_lo[FOUT * NROWS];

// ---- helpers ----------------------------------------------------------------
__device__ __forceinline__ uint32_t s2u(const void* p) {
    uint32_t a;
    asm("{.reg .u64 t; cvta.to.shared.u64 t,%1; cvt.u32.u64 %0,t;}" : "=r"(a) : "l"(p));
    return a;
}
__device__ __forceinline__ float ex2f(float x) {
    float y; asm("ex2.approx.ftz.f32 %0,%1;" : "=f"(y) : "f"(x)); return y;
}
// packed f16x2: lo half = a, hi half = b
__device__ __forceinline__ uint32_t h2pk(float a, float b) {
    uint32_t r; asm("cvt.rn.f16x2.f32 %0,%2,%1;" : "=r"(r) : "f"(a), "f"(b)); return r;
}
__device__ __forceinline__ void cpasync16(uint32_t d, const void* s) {
    asm volatile("cp.async.cg.shared.global [%0],[%1],16;" :: "r"(d), "l"(s));
}
__device__ __forceinline__ void ldsm4(uint32_t* r, uint32_t a) {
    asm volatile("ldmatrix.sync.aligned.m8n8.x4.shared.b16 {%0,%1,%2,%3},[%4];"
                 : "=r"(r[0]), "=r"(r[1]), "=r"(r[2]), "=r"(r[3]) : "r"(a));
}
__device__ __forceinline__ void mmah(float* d, const uint32_t* a, const uint32_t* b) {
    asm volatile("mma.sync.aligned.m16n8k16.row.col.f32.f16.f16.f32 "
                 "{%0,%1,%2,%3},{%4,%5,%6,%7},{%8,%9},{%0,%1,%2,%3};"
                 : "+f"(d[0]), "+f"(d[1]), "+f"(d[2]), "+f"(d[3])
                 : "r"(a[0]), "r"(a[1]), "r"(a[2]), "r"(a[3]), "r"(b[0]), "r"(b[1]));
}
__device__ __forceinline__ ull packf2(float a, float b) {
    ull r;
    asm("mov.b64 %0,{%1,%2};" : "=l"(r) : "r"(__float_as_uint(a)), "r"(__float_as_uint(b)));
    return r;
}
__device__ __forceinline__ void fmaf2(ull& acc, ull a, ull b) {
    asm("fma.rn.f32x2 %0,%1,%2,%0;" : "+l"(acc) : "l"(a), "l"(b));
}
__device__ __forceinline__ void unpackf2(ull v, float& lo, float& hi) {
    uint32_t l, h;
    asm("mov.b64 {%0,%1},%2;" : "=r"(l), "=r"(h) : "l"(v));
    lo = __uint_as_float(l); hi = __uint_as_float(h);
}

// masked exp (wh1/wh2 pre-scaled by L2E): p = adj ? 2^(max(z, 0.2z)) : 0
__device__ __forceinline__ float mexp(float wh1, float wh2, int a) {
    float z = wh1 + wh2;
    float t = fmaxf(z, 0.2f * z);
    if (a == 0) t = __int_as_float(0xff800000);
    return ex2f(t);
}

// ---------------------------------------------------------------------------
// Fused prep (32 rows/block, grid 256): Wh = x@W -> WhT fp16 hi/lo,
// Wh1*L2E, Wh2*L2E.
// ---------------------------------------------------------------------------
__global__ __launch_bounds__(256) void wh_fused(const float* __restrict__ x,
                                                const float* __restrict__ W,
                                                const float* __restrict__ a) {
    extern __shared__ float shm[];
    float* xs = shm;                  // 32 x 132 = 4224
    float* Ws = shm + 4224;           // 128 x 64 = 8192
    float* av = shm + 4224 + 8192;    // 128
    int tid = threadIdx.x;
    int row0 = blockIdx.x * 32;

    for (int u = tid; u < 1024; u += 256) {
        int rr = u >> 5, cc = u & 31;
        float4 v = ((const float4*)(x + (size_t)(row0 + rr) * FIN))[cc];
        *(float4*)(xs + rr * 132 + cc * 4) = v;
    }
    for (int u = tid; u < 2048; u += 256)
        ((float4*)Ws)[u] = ((const float4*)W)[u];
    if (tid < 128) av[tid] = a[tid];
    __syncthreads();

    int tr = tid >> 4, tc = tid & 15;       // tr 0..15 -> rows tr*2+i
    ull acc[2][2] = {{0ull, 0ull}, {0ull, 0ull}};
    const ulonglong2* W2 = (const ulonglong2*)Ws;
#pragma unroll 4
    for (int k = 0; k < FIN; k++) {
        ulonglong2 wv = W2[k * 16 + tc];
#pragma unroll
        for (int i = 0; i < 2; i++) {
            float xv = xs[(tr * 2 + i) * 132 + k];
            ull xp = packf2(xv, xv);
            fmaf2(acc[i][0], xp, wv.x);
            fmaf2(acc[i][1], xp, wv.y);
        }
    }
    float o[2][4];
#pragma unroll
    for (int i = 0; i < 2; i++) {
        unpackf2(acc[i][0], o[i][0], o[i][1]);
        unpackf2(acc[i][1], o[i][2], o[i][3]);
    }
    __syncthreads();
    float* s2 = xs;                  // reuse: [64 f][pitch 33], 2112 floats
#pragma unroll
    for (int i = 0; i < 2; i++)
#pragma unroll
        for (int j = 0; j < 4; j++)
            s2[(tc * 4 + j) * 33 + tr * 2 + i] = o[i][j];
    __syncthreads();

    {
        int f = tid >> 2, seg = tid & 3;     // f 0..63, seg -> cols seg*8..+7
        const float* src = s2 + f * 33 + seg * 8;
        uint32_t hi[4], lo[4];
#pragma unroll
        for (int j = 0; j < 4; j++) {
            float v0 = src[2 * j], v1 = src[2 * j + 1];
            __half h0 = __float2half_rn(v0);
            __half h1 = __float2half_rn(v1);
            hi[j] = ((uint32_t)__half_as_ushort(h1) << 16) | __half_as_ushort(h0);
            lo[j] = h2pk(v0 - __half2float(h0), v1 - __half2float(h1));
        }
        size_t o0 = ((size_t)f * NROWS + row0 + seg * 8) * 2;
        *(uint4*)((char*)g_WhT_hi + o0) = make_uint4(hi[0], hi[1], hi[2], hi[3]);
        *(uint4*)((char*)g_WhT_lo + o0) = make_uint4(lo[0], lo[1], lo[2], lo[3]);
    }
    {
        int row = tid >> 3, sub = tid & 7;   // row 0..31, 8 lanes per row
        float s1 = 0.f, sB = 0.f;
#pragma unroll
        for (int k = 0; k < 8; k++) {
            int f = sub * 8 + k;
            float v = s2[f * 33 + row];
            s1 += v * av[f];
            sB += v * av[64 + f];
        }
        s1 += __shfl_xor_sync(0xffffffffu, s1, 1);
        s1 += __shfl_xor_sync(0xffffffffu, s1, 2);
        s1 += __shfl_xor_sync(0xffffffffu, s1, 4);
        sB += __shfl_xor_sync(0xffffffffu, sB, 1);
        sB += __shfl_xor_sync(0xffffffffu, sB, 2);
        sB += __shfl_xor_sync(0xffffffffu, sB, 4);
        if (sub == 0) {
            g_Wh1[row0 + row] = s1 * L2E;    // prescaled
            g_Wh2[row0 + row] = sB * L2E;    // prescaled
        }
    }
}

// ---------------------------------------------------------------------------
// attn: R15 skeleton (128.99us best), fp16x2 MMA core.
// P single fp16 (A operand), Wh fp16 hi+lo planes: 2 products per fragment.
// BI=32, grid 256, 2 blocks/SM. 8 warps = 2m x 4k; n=64 unsplit.
// ---------------------------------------------------------------------------
__global__ __launch_bounds__(256, 2) void attn_kernel(const int* __restrict__ adj,
                                                      float* __restrict__ out) {
    extern __shared__ char smc[];
    uint32_t smb = s2u(smc);
    float* lred = (float*)(smc + SM_LR);      // [4 kk][32 rows]

    int tid = threadIdx.x;
    int warp = tid >> 5, lane = tid & 31;
    int g = lane >> 2, tg = lane & 3;
    int mi = warp & 1, kk = warp >> 1;        // 2 m-strips x 4 k-chunks
    int i0 = blockIdx.x * BI;
    int row0 = i0 + mi * 16 + g;              // thread's two rows: row0, row0+8

    float wh1a = g_Wh1[row0];
    float wh1b = g_Wh1[row0 + 8];

    const int* ar0 = adj + (size_t)row0 * NROWS;
    const int* ar1 = ar0 + (size_t)8 * NROWS;

    // B ldsm addressing (proven layout)
    uint32_t boff = (uint32_t)(((lane & 7) + 8 * (lane >> 4)) * PB + ((lane >> 3) & 1) * 16);
    uint32_t bBase = smb + SM_WH + boff + (uint32_t)kk * 64;

    float acc[8][4];
#pragma unroll
    for (int i = 0; i < 8; i++)
#pragma unroll
        for (int j = 0; j < 4; j++) acc[i][j] = 0.f;

    // cp.async geometry: Wh 4 chunks/thread/plane
    uint32_t dsto[4], srco[4];
#pragma unroll
    for (int u = 0; u < 4; u++) {
        int idx = u * 256 + tid;
        int row = idx >> 4, ch = idx & 15;
        dsto[u] = (uint32_t)(row * PB + ch * 16);
        srco[u] = (uint32_t)((row * NROWS + ch * 8) * 2);
    }

    // prologue: cp.async Wh(0) -> buf0
    {
        const char* ph = (const char*)g_WhT_hi;
        const char* pl = (const char*)g_WhT_lo;
        uint32_t d0 = smb + SM_WH;
#pragma unroll
        for (int u = 0; u < 4; u++) cpasync16(d0 + dsto[u], ph + srco[u]);
#pragma unroll
        for (int u = 0; u < 4; u++) cpasync16(d0 + 17408 + dsto[u], pl + srco[u]);
        asm volatile("cp.async.commit_group;" ::: "memory");
    }

    float lsum0 = 0.f, lsum1 = 0.f;

    for (int t = 0; t < TILES; ++t) {
        // ---- phase 1: A fragments (single fp16 P) in registers ----
        uint32_t ah[2][4];
        int jb = (t << 7) + kk * 32;
#pragma unroll
        for (int s = 0; s < 4; s++) {          // s = step*2 + half
            int cj = jb + s * 8 + tg * 2;
            int2 A0 = *(const int2*)(ar0 + cj);
            int2 A1 = *(const int2*)(ar1 + cj);
            float2 w2 = *(const float2*)(g_Wh2 + cj);
            float p00 = mexp(wh1a, w2.x, A0.x);
            float p01 = mexp(wh1a, w2.y, A0.y);
            float p10 = mexp(wh1b, w2.x, A1.x);
            float p11 = mexp(wh1b, w2.y, A1.y);
            lsum0 += p00 + p01;
            lsum1 += p10 + p11;
            int st = s >> 1, hf = s & 1;
            ah[st][hf * 2 + 0] = h2pk(p00, p01);
            ah[st][hf * 2 + 1] = h2pk(p10, p11);
        }

        // ---- Wh(t) ready; release buffers ----
        asm volatile("cp.async.wait_group 0;" ::: "memory");
        __syncthreads();
        if (t < 63) {
            uint32_t d0 = smb + SM_WH + (uint32_t)((t + 1) & 1) * 34816;
            const char* ph = (const char*)g_WhT_hi;
            const char* pl = (const char*)g_WhT_lo;
            uint32_t j2 = (uint32_t)(t + 1) * 256;
#pragma unroll
            for (int u = 0; u < 4; u++) cpasync16(d0 + dsto[u], ph + srco[u] + j2);
#pragma unroll
            for (int u = 0; u < 4; u++) cpasync16(d0 + 17408 + dsto[u], pl + srco[u] + j2);
            asm volatile("cp.async.commit_group;" ::: "memory");
        }

        // ---- MMA(t): A regs x Wh[t&1], 2 products (hi+lo planes) ----
        uint32_t wB = bBase + (uint32_t)(t & 1) * 34816;
#pragma unroll
        for (int st = 0; st < 2; st++) {
            uint32_t ko = (uint32_t)st * 32;
#pragma unroll
            for (int ng = 0; ng < 4; ng++) {
                uint32_t bh[4], bl[4];
                uint32_t ba = wB + (uint32_t)ng * (16 * PB) + ko;
                ldsm4(bh, ba);
                ldsm4(bl, ba + 17408);
                mmah(acc[2 * ng + 0], ah[st], bh + 0);
                mmah(acc[2 * ng + 1], ah[st], bh + 2);
                mmah(acc[2 * ng + 0], ah[st], bl + 0);
                mmah(acc[2 * ng + 1], ah[st], bl + 2);
            }
        }
    }

    // ---- epilogue ----
    lsum0 += __shfl_xor_sync(0xffffffffu, lsum0, 1);
    lsum0 += __shfl_xor_sync(0xffffffffu, lsum0, 2);
    lsum1 += __shfl_xor_sync(0xffffffffu, lsum1, 1);
    lsum1 += __shfl_xor_sync(0xffffffffu, lsum1, 2);
    int rl = mi * 16 + g;
    if (tg == 0) {
        lred[kk * 32 + rl] = lsum0;
        lred[kk * 32 + rl + 8] = lsum1;
    }
    __syncthreads();

    float* Red = (float*)(smc + SM_WH);   // reuse: 2 arrays of 32x66 floats
    if (kk == 1 || kk == 3) {
        float* R = Red + (kk >> 1) * 2112;
#pragma unroll
        for (int nb = 0; nb < 8; nb++) {
            int cl = nb * 8 + tg * 2;
            *(float2*)(R + rl * 66 + cl) = make_float2(acc[nb][0], acc[nb][1]);
            *(float2*)(R + (rl + 8) * 66 + cl) = make_float2(acc[nb][2], acc[nb][3]);
        }
    }
    __syncthreads();
    if (kk == 0 || kk == 2) {
        float* R = Red + (kk >> 1) * 2112;
#pragma unroll
        for (int nb = 0; nb < 8; nb++) {
            int cl = nb * 8 + tg * 2;
            float2 o0 = *(float2*)(R + rl * 66 + cl);
            float2 o1 = *(float2*)(R + (rl + 8) * 66 + cl);
            acc[nb][0] += o0.x; acc[nb][1] += o0.y;
            acc[nb][2] += o1.x; acc[nb][3] += o1.y;
        }
    }
    __syncthreads();
    if (kk == 2) {
        float* R = Red + 2112;
#pragma unroll
        for (int nb = 0; nb < 8; nb++) {
            int cl = nb * 8 + tg * 2;
            *(float2*)(R + rl * 66 + cl) = make_float2(acc[nb][0], acc[nb][1]);
            *(float2*)(R + (rl + 8) * 66 + cl) = make_float2(acc[nb][2], acc[nb][3]);
        }
    }
    __syncthreads();
    if (kk == 0) {
        float la = lred[rl] + lred[32 + rl] + lred[64 + rl] + lred[96 + rl];
        float lb = lred[rl + 8] + lred[32 + rl + 8] + lred[64 + rl + 8] + lred[96 + rl + 8];
        float inv0 = 1.0f / la, inv1 = 1.0f / lb;
        float* R = Red + 2112;
#pragma unroll
        for (int nb = 0; nb < 8; nb++) {
            int cl = nb * 8 + tg * 2;
            float2 o0 = *(float2*)(R + rl * 66 + cl);
            float2 o1 = *(float2*)(R + (rl + 8) * 66 + cl);
            float v0 = (acc[nb][0] + o0.x) * inv0;
            float v1 = (acc[nb][1] + o0.y) * inv0;
            float v2 = (acc[nb][2] + o1.x) * inv1;
            float v3 = (acc[nb][3] + o1.y) * inv1;
            v0 = v0 > 0.f ? v0 : (__expf(v0) - 1.f);
            v1 = v1 > 0.f ? v1 : (__expf(v1) - 1.f);
            v2 = v2 > 0.f ? v2 : (__expf(v2) - 1.f);
            v3 = v3 > 0.f ? v3 : (__expf(v3) - 1.f);
            *(float2*)(out + (size_t)(i0 + rl) * FOUT + cl) = make_float2(v0, v1);
            *(float2*)(out + (size_t)(i0 + rl + 8) * FOUT + cl) = make_float2(v2, v3);
        }
    }
}

// ---------------------------------------------------------------------------
extern "C" void kernel_launch(void* const* d_in, const int* in_sizes, int n_in,
                              void* d_out, int out_size) {
    const float* x   = (const float*)d_in[0];
    const int*   adj = (const int*)d_in[1];
    const float* W   = (const float*)d_in[2];
    const float* a   = (const float*)d_in[3];
    float* out = (float*)d_out;

    size_t smem_wh = (size_t)(4224 + 8192 + 128) * sizeof(float);
    static int attr_set = 0;
    if (!attr_set) {
        cudaFuncSetAttribute(wh_fused, cudaFuncAttributeMaxDynamicSharedMemorySize,
                             (int)smem_wh);
        cudaFuncSetAttribute(attn_kernel, cudaFuncAttributeMaxDynamicSharedMemorySize,
                             SM_TOTB);
        attr_set = 1;
    }

    wh_fused<<<NROWS / 32, 256, smem_wh>>>(x, W, a);
    attn_kernel<<<NROWS / BI, 256, SM_TOTB>>>(adj, out);
}